// round 2
// baseline (speedup 1.0000x reference)
#include <cuda_runtime.h>
#include <cuda_bf16.h>
#include <cstring>

// Problem constants
#define N_TOK 16384      // 32*512 tokens
#define DIM   512
#define NE    8192       // codebook size

// Output layout (concatenated, float32):
// loss(1) | z_q_st(16384*512) | perplexity(1) | min_encodings(16384*8192) | idx(16384)
#define OFF_LOSS   0
#define OFF_ZQ     1
#define OFF_PERP   8388609
#define OFF_MINENC 8388610LL
#define OFF_IDX    142606338LL

// Main-kernel tiling
#define TM 64
#define TN 64
#define BK 64
#define SMEM_MAIN ((TM*DIM + BK*TN) * sizeof(float))   // 147456 B

// ---------------- device globals (scratch; no runtime allocation allowed) ------------
__device__ float  g_embT[DIM * NE];     // transposed codebook [k][c]
__device__ float  g_zsum[N_TOK];        // ||z_n||^2
__device__ float  g_esum[NE];           // ||e_c||^2
__device__ int    g_idx[N_TOK];         // argmin indices
__device__ int    g_counts[NE];         // histogram
__device__ double g_loss;               // sum of (z_q - z)^2

// ---------------- f32x2 packed helpers (Blackwell FFMA2) -----------------------------
__device__ __forceinline__ unsigned long long dup2(float x) {
    unsigned long long r;
    asm("mov.b64 %0, {%1, %1};" : "=l"(r) : "f"(x));
    return r;
}
__device__ __forceinline__ void fma2(unsigned long long &d, unsigned long long a,
                                     unsigned long long b) {
    asm("fma.rn.f32x2 %0, %1, %2, %0;" : "+l"(d) : "l"(a), "l"(b));
}
__device__ __forceinline__ float2 unpack2(unsigned long long v) {
    float2 f;
    asm("mov.b64 {%0, %1}, %2;" : "=f"(f.x), "=f"(f.y) : "l"(v));
    return f;
}

// ---------------- small kernels -------------------------------------------------------
__global__ void k_zero() {
    int i = blockIdx.x * 256 + threadIdx.x;
    if (i < NE) g_counts[i] = 0;
    if (i == 0) g_loss = 0.0;
}

// transpose emb [NE, DIM] -> g_embT [DIM, NE]
__global__ void k_transpose(const float* __restrict__ emb) {
    __shared__ float t[32][33];
    int k0 = blockIdx.x * 32, c0 = blockIdx.y * 32;
    int tx = threadIdx.x, ty = threadIdx.y;           // 32 x 8
    #pragma unroll
    for (int i = 0; i < 32; i += 8)
        t[ty + i][tx] = emb[(size_t)(c0 + ty + i) * DIM + k0 + tx];
    __syncthreads();
    #pragma unroll
    for (int i = 0; i < 32; i += 8)
        g_embT[(size_t)(k0 + ty + i) * NE + c0 + tx] = t[tx][ty + i];
}

// row-wise sum of squares; which=1 -> g_zsum, which=0 -> g_esum
__global__ void k_rowsum(const float* __restrict__ src, int nrows, int which) {
    int row = blockIdx.x * 8 + (threadIdx.x >> 5);
    int lane = threadIdx.x & 31;
    if (row >= nrows) return;
    const float* p = src + (size_t)row * DIM;
    float s = 0.f;
    #pragma unroll
    for (int i = 0; i < DIM / 32; i++) {
        float v = p[lane + 32 * i];
        s = fmaf(v, v, s);
    }
    #pragma unroll
    for (int o = 16; o > 0; o >>= 1) s += __shfl_xor_sync(0xffffffffu, s, o);
    if (lane == 0) {
        if (which) g_zsum[row] = s;
        else       g_esum[row] = s;
    }
}

// ---------------- fused fp32 GEMM + argmin -------------------------------------------
__global__ __launch_bounds__(256, 1)
void k_main(const float* __restrict__ z, float* __restrict__ out) {
    extern __shared__ float smem[];
    float* zs = smem;                 // [TM][DIM] row-major, persistent
    float* es = smem + TM * DIM;      // [BK][TN] k-major, streamed

    int tid = threadIdx.x;
    int tx = tid & 15;                // code group (4 codes)
    int ty = tid >> 4;                // row group  (4 rows)
    int row0 = blockIdx.x * TM;

    // load 64 rows of z into smem (vectorized, coalesced, conflict-free)
    for (int v = tid; v < TM * (DIM / 4); v += 256) {
        int row = v >> 7, kq = v & 127;
        reinterpret_cast<float4*>(zs + row * DIM)[kq] =
            reinterpret_cast<const float4*>(z + (size_t)(row0 + row) * DIM)[kq];
    }

    float zsumr[4];
    #pragma unroll
    for (int i = 0; i < 4; i++) zsumr[i] = g_zsum[row0 + ty * 4 + i];

    float bv[4];
    int   bi[4];
    #pragma unroll
    for (int i = 0; i < 4; i++) { bv[i] = 3.4e38f; bi[i] = 0; }

    unsigned long long acc[4][2];

    for (int ct = 0; ct < NE / TN; ct++) {
        int c0 = ct * TN;
        #pragma unroll
        for (int i = 0; i < 4; i++) { acc[i][0] = 0ull; acc[i][1] = 0ull; }

        for (int ks = 0; ks < DIM / BK; ks++) {
            int kb = ks * BK;
            __syncthreads();
            // stage emb tile [BK x TN] from transposed codebook (coalesced)
            for (int v = tid; v < BK * (TN / 4); v += 256) {
                int kk = v >> 4, c4 = v & 15;
                *reinterpret_cast<float4*>(es + kk * TN + c4 * 4) =
                    *reinterpret_cast<const float4*>(
                        g_embT + (size_t)(kb + kk) * NE + c0 + c4 * 4);
            }
            __syncthreads();

            const float* zr = zs + (ty * 4) * DIM + kb;
            const float* ep = es + tx * 4;
            #pragma unroll 8
            for (int kk = 0; kk < BK; kk++) {
                ulonglong2 re = *reinterpret_cast<const ulonglong2*>(ep + kk * TN);
                #pragma unroll
                for (int i = 0; i < 4; i++) {
                    unsigned long long a = dup2(zr[i * DIM + kk]);
                    fma2(acc[i][0], a, re.x);
                    fma2(acc[i][1], a, re.y);
                }
            }
        }

        // epilogue: d = (zsum + esum) - 2*s , running argmin (first-index ties)
        int cb = c0 + tx * 4;
        float e0 = __ldg(g_esum + cb + 0);
        float e1 = __ldg(g_esum + cb + 1);
        float e2 = __ldg(g_esum + cb + 2);
        float e3 = __ldg(g_esum + cb + 3);
        #pragma unroll
        for (int i = 0; i < 4; i++) {
            float2 p0 = unpack2(acc[i][0]);
            float2 p1 = unpack2(acc[i][1]);
            float d0 = (zsumr[i] + e0) - 2.f * p0.x;
            float d1 = (zsumr[i] + e1) - 2.f * p0.y;
            float d2 = (zsumr[i] + e2) - 2.f * p1.x;
            float d3 = (zsumr[i] + e3) - 2.f * p1.y;
            if (d0 < bv[i]) { bv[i] = d0; bi[i] = cb + 0; }
            if (d1 < bv[i]) { bv[i] = d1; bi[i] = cb + 1; }
            if (d2 < bv[i]) { bv[i] = d2; bi[i] = cb + 2; }
            if (d3 < bv[i]) { bv[i] = d3; bi[i] = cb + 3; }
        }
    }

    // cross-thread argmin reduce (reuse es region)
    __syncthreads();
    float* rv = es;                         // [TM][16]
    int*   ri = reinterpret_cast<int*>(es + TM * 16);
    #pragma unroll
    for (int i = 0; i < 4; i++) {
        rv[(ty * 4 + i) * 16 + tx] = bv[i];
        ri[(ty * 4 + i) * 16 + tx] = bi[i];
    }
    __syncthreads();
    if (tid < TM) {
        float best = rv[tid * 16];
        int bidx = ri[tid * 16];
        #pragma unroll
        for (int t2 = 1; t2 < 16; t2++) {
            float v = rv[tid * 16 + t2];
            int id  = ri[tid * 16 + t2];
            if (v < best || (v == best && id < bidx)) { best = v; bidx = id; }
        }
        int row = row0 + tid;
        g_idx[row] = bidx;
        out[OFF_IDX + row] = (float)bidx;
        out[OFF_MINENC + (long long)row * NE + bidx] = 1.0f;
        atomicAdd(&g_counts[bidx], 1);
    }
}

// ---------------- gather + straight-through + loss -----------------------------------
__global__ void k_zq(const float* __restrict__ z, const float* __restrict__ emb,
                     float* __restrict__ out) {
    __shared__ double wsum[4];
    int row = blockIdx.x;
    int e = g_idx[row];
    int j = threadIdx.x;    // 128 threads, 4 elems each
    float4 zv = reinterpret_cast<const float4*>(z + (size_t)row * DIM)[j];
    float4 ev = reinterpret_cast<const float4*>(emb + (size_t)e * DIM)[j];
    float t0 = ev.x - zv.x, t1 = ev.y - zv.y, t2 = ev.z - zv.z, t3 = ev.w - zv.w;
    float* o = out + OFF_ZQ + (size_t)row * DIM + j * 4;   // 4B aligned only (OFF_ZQ=1)
    o[0] = zv.x + t0;
    o[1] = zv.y + t1;
    o[2] = zv.z + t2;
    o[3] = zv.w + t3;
    double s = (double)t0 * t0 + (double)t1 * t1 + (double)t2 * t2 + (double)t3 * t3;
    #pragma unroll
    for (int off = 16; off; off >>= 1) s += __shfl_xor_sync(0xffffffffu, s, off);
    if ((j & 31) == 0) wsum[j >> 5] = s;
    __syncthreads();
    if (j == 0) atomicAdd(&g_loss, wsum[0] + wsum[1] + wsum[2] + wsum[3]);
}

// ---------------- perplexity + loss finalize ------------------------------------------
__global__ void k_final(float* __restrict__ out) {
    __shared__ float red[256];
    int t = threadIdx.x;
    float acc = 0.f;
    for (int i = t; i < NE; i += 256) {
        float em = (float)g_counts[i] * (1.0f / (float)N_TOK);
        acc += em * logf(em + 1e-10f);
    }
    red[t] = acc;
    __syncthreads();
    for (int s = 128; s > 0; s >>= 1) {
        if (t < s) red[t] += red[t + s];
        __syncthreads();
    }
    if (t == 0) {
        out[OFF_PERP] = expf(-red[0]);
        out[OFF_LOSS] = (float)(1.25 * g_loss * (1.0 / (double)(N_TOK * DIM)));
    }
}

// ---------------- launch --------------------------------------------------------------
extern "C" void kernel_launch(void* const* d_in, const int* in_sizes, int n_in,
                              void* d_out, int out_size) {
    const float* z   = (const float*)d_in[0];
    const float* emb = (const float*)d_in[1];
    float* out = (float*)d_out;

    // one-time attribute set (runs during the correctness call, before capture)
    static bool attr_done = []() {
        cudaFuncSetAttribute(k_main, cudaFuncAttributeMaxDynamicSharedMemorySize,
                             (int)SMEM_MAIN);
        return true;
    }();
    (void)attr_done;

    // zero the one-hot region (poisoned 0xAA by harness)
    cudaMemsetAsync(out + OFF_MINENC, 0, (size_t)N_TOK * NE * sizeof(float));
    k_zero<<<32, 256>>>();
    k_transpose<<<dim3(DIM / 32, NE / 32), dim3(32, 8)>>>(emb);
    k_rowsum<<<N_TOK / 8, 256>>>(z, N_TOK, 1);
    k_rowsum<<<NE / 8, 256>>>(emb, NE, 0);
    k_main<<<N_TOK / TM, 256, SMEM_MAIN>>>(z, out);
    k_zq<<<N_TOK, 128>>>(z, emb, out);
    k_final<<<1, 256>>>(out);
}